// round 5
// baseline (speedup 1.0000x reference)
#include <cuda_runtime.h>
#include <math.h>
#include <stdint.h>

#define NEGC 1.0e9f
typedef unsigned long long ull;

// ==================== static scratch ====================
__device__ float g_epart[64 * 128];
__device__ float g_emean[128];
__device__ float g_Bmat[4096 * 128];
__device__ float g_qz[512 * 128];
__device__ float g_U[2 * 512 * 1024];
__device__ float g_qhn[4 * 8 * 128 * 128];
__device__ float g_qhnT[4 * 8 * 128 * 128];
__device__ float g_S[512 * 4096];
__device__ float g_Gpart[8 * 512 * 128];
__device__ float g_ET[128 * 32000];          // E transposed (fp32)
__device__ float g_SEpart[50 * 512 * 128];
__device__ float g_SEsum[50 * 512];

// ---- f32x2 helpers ----
__device__ __forceinline__ ull pk2(float lo, float hi) {
    ull r; asm("mov.b64 %0, {%1, %2};" : "=l"(r) : "f"(lo), "f"(hi)); return r;
}
__device__ __forceinline__ void fma2(ull &d, ull a, ull b) {
    asm("fma.rn.f32x2 %0, %1, %2, %3;" : "=l"(d) : "l"(a), "l"(b), "l"(d));
}
__device__ __forceinline__ void upk(ull v, float &lo, float &hi) {
    asm("mov.b64 {%0, %1}, %2;" : "=f"(lo), "=f"(hi) : "l"(v));
}

// ==================== setup ====================
__global__ void k_emean_part(const float* __restrict__ E) {
    int b = blockIdx.x, t = threadIdx.x;
    int d = t & 127, h = t >> 7;
    float s = 0.f;
    for (int v = b * 500 + h; v < b * 500 + 500; v += 2) s += E[v * 128 + d];
    __shared__ float sh[256];
    sh[t] = s; __syncthreads();
    if (t < 128) g_epart[b * 128 + t] = sh[t] + sh[t + 128];
}
__global__ void k_emean_red() {
    int t = threadIdx.x;
    float s = 0.f;
    for (int b = 0; b < 64; b++) s += g_epart[b * 128 + t];
    g_emean[t] = s * (1.0f / 32000.0f);
}

__global__ void k_bmat(const float* __restrict__ T) {
    int idx = blockIdx.x * 256 + threadIdx.x;
    if (idx >= 4096 * 128) return;
    int r = idx >> 7, col = idx & 127;
    float val;
    if (r < 2048) {
        int k = r >> 10, c = (r >> 7) & 7, b = r & 127;
        val = T[((k * 128 + col) * 128 + b) * 8 + c];
    } else {
        int r2 = r - 2048;
        int k = r2 >> 10, c = (r2 >> 7) & 7, a = r2 & 127;
        val = T[((k * 128 + a) * 128 + col) * 8 + c];
    }
    g_Bmat[idx] = val;
}

// transpose E -> g_ET[d][v]. grid (250, 4), 256 thr
__global__ void k_transE(const float* __restrict__ E) {
    __shared__ float tile[128][33];
    int v0 = blockIdx.x * 128, d0 = blockIdx.y * 32, t = threadIdx.x;
    for (int idx = t; idx < 4096; idx += 256) {
        int r = idx >> 5, c = idx & 31;
        tile[r][c] = E[(size_t)(v0 + r) * 128 + d0 + c];
    }
    __syncthreads();
    for (int idx = t; idx < 4096; idx += 256) {
        int d = idx >> 7, vv = idx & 127;
        g_ET[(size_t)(d0 + d) * 32000 + v0 + vv] = tile[vv][d];
    }
}

// ---- 128-wide softmax (block of 128 thr) ----
__device__ __forceinline__ float softmax128(float raw, float* r1, float* r2) {
    int lane = threadIdx.x & 31, w = threadIdx.x >> 5;
    float m = raw;
    #pragma unroll
    for (int o = 16; o; o >>= 1) m = fmaxf(m, __shfl_xor_sync(~0u, m, o));
    if (lane == 0) r1[w] = m;
    __syncthreads();
    m = fmaxf(fmaxf(r1[0], r1[1]), fmaxf(r1[2], r1[3]));
    float e = __expf(raw - m), s = e;
    #pragma unroll
    for (int o = 16; o; o >>= 1) s += __shfl_xor_sync(~0u, s, o);
    if (lane == 0) r2[w] = s;
    __syncthreads();
    return e / (r2[0] + r2[1] + r2[2] + r2[3]);
}

__global__ void k_init_qz(const float* __restrict__ x, const int* __restrict__ mask,
                          const int* __restrict__ mmask) {
    int zi = blockIdx.x, a = threadIdx.x;
    __shared__ float r1[4], r2[4];
    float keep = mask[zi] ? 1.f : 0.f;
    float mm = (float)mmask[zi];
    float raw = (x[zi * 128 + a] * (1.f - mm) + g_emean[a] * mm) * keep;
    float p = softmax128(raw, r1, r2);
    g_qz[zi * 128 + a] = p * keep;
}

// ==================== small FFMA GEMMs (unchanged, passing) ====================
__global__ void __launch_bounds__(256) k_nn64(const float* __restrict__ T, int which) {
    const float *A, *B; float *C;
    int lda, ldb, ldc, ksteps, kb;
    if (which == 0) {
        int kk = blockIdx.z;
        A = g_qz; lda = 128; B = T + kk * 131072; ldb = 1024;
        C = g_U + (size_t)kk * 524288; ldc = 1024; ksteps = 8; kb = 0;
    } else {
        int ks = blockIdx.z;
        A = g_S; lda = 4096; B = g_Bmat; ldb = 128;
        C = g_Gpart + (size_t)ks * 65536; ldc = 128; ksteps = 32; kb = ks * 512;
    }
    int m0 = blockIdx.y * 64, n0 = blockIdx.x * 64;
    __shared__ float As[16][68], Bs[16][64];
    int t = threadIdx.x, tm = t >> 4, tn = t & 15;
    ull acc[4][2];
    #pragma unroll
    for (int i = 0; i < 4; i++) { acc[i][0] = pk2(0.f, 0.f); acc[i][1] = pk2(0.f, 0.f); }
    for (int s = 0; s < ksteps; s++) {
        int k0 = kb + s * 16;
        { int r = t >> 2, c4 = (t & 3) * 4;
          float4 av = *(const float4*)&A[(size_t)(m0 + r) * lda + k0 + c4];
          As[c4][r] = av.x; As[c4 + 1][r] = av.y; As[c4 + 2][r] = av.z; As[c4 + 3][r] = av.w; }
        { int r = t >> 4, c4 = (t & 15) * 4;
          *(float4*)&Bs[r][c4] = *(const float4*)&B[(size_t)(k0 + r) * ldb + n0 + c4]; }
        __syncthreads();
        #pragma unroll
        for (int p = 0; p < 16; p++) {
            float4 a = *(const float4*)&As[p][tm * 4];
            float4 b = *(const float4*)&Bs[p][tn * 4];
            ull b01 = pk2(b.x, b.y), b23 = pk2(b.z, b.w);
            ull a0 = pk2(a.x, a.x), a1 = pk2(a.y, a.y), a2 = pk2(a.z, a.z), a3 = pk2(a.w, a.w);
            fma2(acc[0][0], a0, b01); fma2(acc[0][1], a0, b23);
            fma2(acc[1][0], a1, b01); fma2(acc[1][1], a1, b23);
            fma2(acc[2][0], a2, b01); fma2(acc[2][1], a2, b23);
            fma2(acc[3][0], a3, b01); fma2(acc[3][1], a3, b23);
        }
        __syncthreads();
    }
    #pragma unroll
    for (int i = 0; i < 4; i++) {
        float c0, c1, c2, c3;
        upk(acc[i][0], c0, c1); upk(acc[i][1], c2, c3);
        *(float4*)&C[(size_t)(m0 + tm * 4 + i) * ldc + n0 + tn * 4] = make_float4(c0, c1, c2, c3);
    }
}

__global__ void __launch_bounds__(256) k_F(const int* __restrict__ mask) {
    int zi = blockIdx.x, z = zi >> 7, i = zi & 127;
    int t = threadIdx.x;
    __shared__ float U_sh[2][1024];
    __shared__ float qz_sh[32][129];
    __shared__ float qh_sh[8][128];
    __shared__ float smax[8], ssum[8];
    for (int idx = t; idx < 2048; idx += 256) {
        int k = idx >> 10, bc = idx & 1023;
        U_sh[k][bc] = g_U[((size_t)k * 512 + zi) * 1024 + bc];
    }
    int j = t & 127, ch = t >> 7;
    int ksel = (j > i) ? 0 : 1;
    float a0 = 0.f, a1 = 0.f, a2 = 0.f, a3 = 0.f;
    const float* qzb = g_qz + z * 128 * 128;
    for (int b0 = 0; b0 < 128; b0 += 32) {
        __syncthreads();
        #pragma unroll
        for (int e = 0; e < 16; e++) {
            int lin = t + e * 256;
            int jj = lin >> 5, col = lin & 31;
            qz_sh[col][jj] = qzb[jj * 128 + b0 + col];
        }
        __syncthreads();
        #pragma unroll 8
        for (int bb = 0; bb < 32; bb++) {
            float qv = qz_sh[bb][j];
            const float* u = &U_sh[ksel][(b0 + bb) * 8 + ch * 4];
            a0 += qv * u[0]; a1 += qv * u[1]; a2 += qv * u[2]; a3 += qv * u[3];
        }
    }
    bool vi = mask[z * 128 + i] != 0, vj = mask[z * 128 + j] != 0;
    if (i == j || !vi || !vj) { a0 = a1 = a2 = a3 = -NEGC; }
    qh_sh[ch * 4 + 0][j] = a0; qh_sh[ch * 4 + 1][j] = a1;
    qh_sh[ch * 4 + 2][j] = a2; qh_sh[ch * 4 + 3][j] = a3;
    __syncthreads();
    int w = t >> 5, lane = t & 31;
    float v0 = qh_sh[w][lane], v1 = qh_sh[w][lane + 32];
    float v2 = qh_sh[w][lane + 64], v3 = qh_sh[w][lane + 96];
    float mx = fmaxf(fmaxf(v0, v1), fmaxf(v2, v3));
    #pragma unroll
    for (int o = 16; o; o >>= 1) mx = fmaxf(mx, __shfl_xor_sync(~0u, mx, o));
    float sum = __expf(v0 - mx) + __expf(v1 - mx) + __expf(v2 - mx) + __expf(v3 - mx);
    #pragma unroll
    for (int o = 16; o; o >>= 1) sum += __shfl_xor_sync(~0u, sum, o);
    if (lane == 0) { smax[w] = mx; ssum[w] = sum; }
    __syncthreads();
    float vals[4] = {a0, a1, a2, a3};
    #pragma unroll
    for (int hh = 0; hh < 4; hh++) {
        int h = ch * 4 + hh;
        float p = __expf(vals[hh] - smax[h]) / ssum[h];
        g_qhn[(((z * 8 + h) * 128 + i) << 7) + j] = p;
        g_qhnT[(((z * 8 + h) * 128 + j) << 7) + i] = p;
    }
}

__global__ void __launch_bounds__(256) k_S() {
    int zi = blockIdx.x, z = zi >> 7, i = zi & 127;
    int t = threadIdx.x;
    __shared__ float wT[128][36];
    __shared__ float qzc[32][128];
    for (int idx = t; idx < 4096; idx += 256) {
        int r = idx & 31, j = idx >> 5;
        float v; bool m;
        if (r < 16) {
            int k = r >> 3, c = r & 7;
            v = g_qhn[(((z * 8 + c) * 128 + i) << 7) + j];
            m = (k == 0) ? (j > i) : (j < i);
        } else {
            int r2 = r - 16, k = r2 >> 3, c = r2 & 7;
            v = g_qhnT[(((z * 8 + c) * 128 + i) << 7) + j];
            m = (k == 0) ? (j < i) : (j > i);
        }
        wT[j][r] = m ? v : 0.f;
    }
    int tm = t >> 5, tn = t & 31;
    ull acc[4][2];
    #pragma unroll
    for (int q = 0; q < 4; q++) { acc[q][0] = pk2(0.f, 0.f); acc[q][1] = pk2(0.f, 0.f); }
    for (int j0 = 0; j0 < 128; j0 += 32) {
        __syncthreads();
        for (int idx = t; idx < 4096; idx += 256) {
            int jl = idx >> 7, b = idx & 127;
            qzc[jl][b] = g_qz[((z * 128) + j0 + jl) * 128 + b];
        }
        __syncthreads();
        #pragma unroll 8
        for (int jl = 0; jl < 32; jl++) {
            float4 wv = *(const float4*)&wT[j0 + jl][tm * 4];
            float4 qv = *(const float4*)&qzc[jl][tn * 4];
            ull q01 = pk2(qv.x, qv.y), q23 = pk2(qv.z, qv.w);
            ull w0 = pk2(wv.x, wv.x), w1 = pk2(wv.y, wv.y), w2 = pk2(wv.z, wv.z), w3 = pk2(wv.w, wv.w);
            fma2(acc[0][0], w0, q01); fma2(acc[0][1], w0, q23);
            fma2(acc[1][0], w1, q01); fma2(acc[1][1], w1, q23);
            fma2(acc[2][0], w2, q01); fma2(acc[2][1], w2, q23);
            fma2(acc[3][0], w3, q01); fma2(acc[3][1], w3, q23);
        }
    }
    #pragma unroll
    for (int q = 0; q < 4; q++) {
        int r = tm * 4 + q;
        int base = (r < 16) ? r * 128 : 2048 + (r - 16) * 128;
        float c0, c1, c2, c3;
        upk(acc[q][0], c0, c1); upk(acc[q][1], c2, c3);
        *(float4*)&g_S[(size_t)zi * 4096 + base + tn * 4] = make_float4(c0, c1, c2, c3);
    }
}

// ---- Z update: reduce Gpart + SE combine, unary mix, softmax ----
__global__ void k_zupd(const float* __restrict__ x, const int* __restrict__ mask,
                       const int* __restrict__ mmask, int useSE) {
    int zi = blockIdx.x, d = threadIdx.x;
    __shared__ float r1[4], r2[4];
    float g = 0.f;
    #pragma unroll
    for (int p = 0; p < 8; p++) g += g_Gpart[((size_t)p * 512 + zi) * 128 + d];
    float se;
    if (useSE) {
        float num = 0.f, den = 0.f;
        for (int s = 0; s < 50; s++) {
            num += g_SEpart[((size_t)s * 512 + zi) * 128 + d];
            den += g_SEsum[s * 512 + zi];
        }
        se = num / den;
    } else se = g_emean[d];
    float mm = (float)mmask[zi];
    float raw = x[zi * 128 + d] * (1.f - mm) + se * mm + g;
    float keep = mask[zi] ? 1.f : 0.f;
    float p_ = softmax128(raw, r1, r2);
    g_qz[zi * 128 + d] = p_ * keep;
}

// ==================== fused SE: SEpart[vs] = sum_v exp(qz@E^T) * E, SEsum rowsums ====
// grid (50, 4), 256 thr, dynamic smem
#define QZT_OFF 0                      // [128 d][132 m]
#define ETD_OFF (128 * 132)            // [128 d][68 v]
#define EVD_OFF (ETD_OFF + 128 * 68)   // [64 v][132 d]
#define PS_OFF  (EVD_OFF + 64 * 132)   // [64 v][132 m]
#define SEF_SMEM ((PS_OFF + 64 * 132) * 4)

__global__ void __launch_bounds__(256) k_sef(const float* __restrict__ E) {
    extern __shared__ float sm[];
    float* qzT = sm + QZT_OFF;
    float* Etd = sm + ETD_OFF;
    float* Evd = sm + EVD_OFF;
    float* Ps  = sm + PS_OFF;
    int t = threadIdx.x;
    int vs = blockIdx.x, m0 = blockIdx.y * 128;
    int vbase = vs * 640;

    // load qz block transposed: qzT[d][m]
    {
        int m = t >> 1, d0 = (t & 1) * 64;
        const float* src = g_qz + (size_t)(m0 + m) * 128 + d0;
        #pragma unroll
        for (int q = 0; q < 16; q++) {
            float4 v = *(const float4*)(src + q * 4);
            qzT[(d0 + q * 4 + 0) * 132 + m] = v.x;
            qzT[(d0 + q * 4 + 1) * 132 + m] = v.y;
            qzT[(d0 + q * 4 + 2) * 132 + m] = v.z;
            qzT[(d0 + q * 4 + 3) * 132 + m] = v.w;
        }
    }

    int tm1 = t >> 4, tv = t & 15;          // GEMM1: 8m x 4v
    int tmg = t >> 4, tdg = t & 15;         // GEMM2: 8m x 8d
    ull acc[8][4];
    #pragma unroll
    for (int i = 0; i < 8; i++)
        #pragma unroll
        for (int q = 0; q < 4; q++) acc[i][q] = pk2(0.f, 0.f);
    float psum[8];
    #pragma unroll
    for (int i = 0; i < 8; i++) psum[i] = 0.f;

    for (int tile = 0; tile < 10; tile++) {
        int vg = vbase + tile * 64;
        __syncthreads();
        // load Etd[d][v] from g_ET
        {
            int d = t >> 1, vq = (t & 1) * 32;
            const float* src = g_ET + (size_t)d * 32000 + vg + vq;
            float* dst = Etd + d * 68 + vq;
            #pragma unroll
            for (int q = 0; q < 8; q++) *(float4*)(dst + q * 4) = *(const float4*)(src + q * 4);
        }
        // load Evd[v][d] from E
        {
            int v = t >> 2, dq = (t & 3) * 32;
            const float* src = E + (size_t)(vg + v) * 128 + dq;
            float* dst = Evd + v * 132 + dq;
            #pragma unroll
            for (int q = 0; q < 8; q++) *(float4*)(dst + q * 4) = *(const float4*)(src + q * 4);
        }
        __syncthreads();
        // GEMM1: L[8m][4v]
        ull L[8][2];
        #pragma unroll
        for (int i = 0; i < 8; i++) { L[i][0] = pk2(0.f, 0.f); L[i][1] = pk2(0.f, 0.f); }
        #pragma unroll 4
        for (int d = 0; d < 128; d++) {
            float4 a0 = *(const float4*)&qzT[d * 132 + tm1 * 8];
            float4 a1 = *(const float4*)&qzT[d * 132 + tm1 * 8 + 4];
            float4 b  = *(const float4*)&Etd[d * 68 + tv * 4];
            ull b01 = pk2(b.x, b.y), b23 = pk2(b.z, b.w);
            float av[8] = {a0.x, a0.y, a0.z, a0.w, a1.x, a1.y, a1.z, a1.w};
            #pragma unroll
            for (int i = 0; i < 8; i++) {
                ull ai = pk2(av[i], av[i]);
                fma2(L[i][0], ai, b01); fma2(L[i][1], ai, b23);
            }
        }
        // exp + write P^T[v][m] + rowsum partials
        #pragma unroll
        for (int i = 0; i < 8; i++) {
            float e0, e1, e2, e3;
            upk(L[i][0], e0, e1); upk(L[i][1], e2, e3);
            e0 = __expf(e0); e1 = __expf(e1); e2 = __expf(e2); e3 = __expf(e3);
            psum[i] += e0 + e1 + e2 + e3;
            int m = tm1 * 8 + i;
            Ps[(tv * 4 + 0) * 132 + m] = e0;
            Ps[(tv * 4 + 1) * 132 + m] = e1;
            Ps[(tv * 4 + 2) * 132 + m] = e2;
            Ps[(tv * 4 + 3) * 132 + m] = e3;
        }
        __syncthreads();
        // GEMM2: acc[8m][8d] += P^T' @ Evd
        #pragma unroll 4
        for (int v = 0; v < 64; v++) {
            float4 a0 = *(const float4*)&Ps[v * 132 + tmg * 8];
            float4 a1 = *(const float4*)&Ps[v * 132 + tmg * 8 + 4];
            float4 b0 = *(const float4*)&Evd[v * 132 + tdg * 8];
            float4 b1 = *(const float4*)&Evd[v * 132 + tdg * 8 + 4];
            ull bb[4] = {pk2(b0.x, b0.y), pk2(b0.z, b0.w), pk2(b1.x, b1.y), pk2(b1.z, b1.w)};
            float av[8] = {a0.x, a0.y, a0.z, a0.w, a1.x, a1.y, a1.z, a1.w};
            #pragma unroll
            for (int i = 0; i < 8; i++) {
                ull ai = pk2(av[i], av[i]);
                fma2(acc[i][0], ai, bb[0]); fma2(acc[i][1], ai, bb[1]);
                fma2(acc[i][2], ai, bb[2]); fma2(acc[i][3], ai, bb[3]);
            }
        }
    }
    // write acc
    #pragma unroll
    for (int i = 0; i < 8; i++) {
        float f[8];
        upk(acc[i][0], f[0], f[1]); upk(acc[i][1], f[2], f[3]);
        upk(acc[i][2], f[4], f[5]); upk(acc[i][3], f[6], f[7]);
        size_t base = ((size_t)vs * 512 + m0 + tmg * 8 + i) * 128 + tdg * 8;
        *(float4*)&g_SEpart[base]     = make_float4(f[0], f[1], f[2], f[3]);
        *(float4*)&g_SEpart[base + 4] = make_float4(f[4], f[5], f[6], f[7]);
    }
    // reduce psum across the 16 v-groups (reuse Etd area: [128 m][17])
    __syncthreads();
    float* red = Etd;
    #pragma unroll
    for (int i = 0; i < 8; i++) red[(tm1 * 8 + i) * 17 + tv] = psum[i];
    __syncthreads();
    if (t < 128) {
        float s = 0.f;
        #pragma unroll
        for (int q = 0; q < 16; q++) s += red[t * 17 + q];
        g_SEsum[vs * 512 + m0 + t] = s;
    }
}

// ==================== final out = qz @ E^T (R3 mode-2 path) ====================
__global__ void __launch_bounds__(256) k_msg(const float* __restrict__ E, float* __restrict__ out) {
    __shared__ float As[8][128], Bs[8][128];
    int t = threadIdx.x;
    int m0 = blockIdx.y * 128, n0 = blockIdx.x * 128;
    int row = t >> 1, kq = (t & 1) * 4;
    int tm = t >> 4, tn = t & 15;
    ull acc[8][4];
    #pragma unroll
    for (int i = 0; i < 8; i++)
        #pragma unroll
        for (int q = 0; q < 4; q++) acc[i][q] = pk2(0.f, 0.f);
    for (int s = 0; s < 16; s++) {
        int k0 = s * 8;
        float4 av = *(const float4*)&g_qz[(m0 + row) * 128 + k0 + kq];
        float4 bv = *(const float4*)&E[(size_t)(n0 + row) * 128 + k0 + kq];
        __syncthreads();
        As[kq][row] = av.x; As[kq + 1][row] = av.y; As[kq + 2][row] = av.z; As[kq + 3][row] = av.w;
        Bs[kq][row] = bv.x; Bs[kq + 1][row] = bv.y; Bs[kq + 2][row] = bv.z; Bs[kq + 3][row] = bv.w;
        __syncthreads();
        #pragma unroll
        for (int p = 0; p < 8; p++) {
            float4 a0 = *(const float4*)&As[p][tm * 8], a1 = *(const float4*)&As[p][tm * 8 + 4];
            float4 b0 = *(const float4*)&Bs[p][tn * 8], b1 = *(const float4*)&Bs[p][tn * 8 + 4];
            ull bb[4] = {pk2(b0.x, b0.y), pk2(b0.z, b0.w), pk2(b1.x, b1.y), pk2(b1.z, b1.w)};
            float avv[8] = {a0.x, a0.y, a0.z, a0.w, a1.x, a1.y, a1.z, a1.w};
            #pragma unroll
            for (int i = 0; i < 8; i++) {
                ull ai = pk2(avv[i], avv[i]);
                fma2(acc[i][0], ai, bb[0]); fma2(acc[i][1], ai, bb[1]);
                fma2(acc[i][2], ai, bb[2]); fma2(acc[i][3], ai, bb[3]);
            }
        }
    }
    #pragma unroll
    for (int i = 0; i < 8; i++) {
        float f[8];
        upk(acc[i][0], f[0], f[1]); upk(acc[i][1], f[2], f[3]);
        upk(acc[i][2], f[4], f[5]); upk(acc[i][3], f[6], f[7]);
        size_t base = (size_t)(m0 + tm * 8 + i) * 32000 + n0 + tn * 8;
        *(float4*)&out[base] = make_float4(f[0], f[1], f[2], f[3]);
        *(float4*)&out[base + 4] = make_float4(f[4], f[5], f[6], f[7]);
    }
}

// ==================== launch ====================
extern "C" void kernel_launch(void* const* d_in, const int* in_sizes, int n_in,
                              void* d_out, int out_size) {
    const float* x    = (const float*)d_in[0];
    const int*   mask = (const int*)d_in[1];
    const float* E    = (const float*)d_in[2];
    const int*   mm   = (const int*)d_in[3];
    const float* T    = (const float*)d_in[4];
    float* out = (float*)d_out;

    cudaFuncSetAttribute(k_sef, cudaFuncAttributeMaxDynamicSharedMemorySize, SEF_SMEM);

    k_emean_part<<<64, 256>>>(E);
    k_emean_red<<<1, 128>>>();
    k_bmat<<<2048, 256>>>(T);
    k_transE<<<dim3(250, 4), 256>>>(E);
    k_init_qz<<<512, 128>>>(x, mask, mm);
    for (int it = 0; it < 4; it++) {
        k_nn64<<<dim3(16, 8, 2), 256>>>(T, 0);     // U = qz @ T[k]
        k_F<<<512, 256>>>(mask);                   // F + softmax -> qhn, qhnT
        k_S<<<512, 256>>>();                       // s1|s2 -> S
        k_nn64<<<dim3(2, 8, 8), 256>>>(T, 1);      // Gpart = S @ Bmat
        k_zupd<<<512, 128>>>(x, mask, mm, it > 0); // z update (+SE combine)
        if (it < 3) k_sef<<<dim3(50, 4), 256, SEF_SMEM>>>(E);   // fused SE
        else        k_msg<<<dim3(250, 4), 256>>>(E, out);       // final output
    }
}

// round 6
// speedup vs baseline: 1.2475x; 1.2475x over previous
#include <cuda_runtime.h>
#include <math.h>
#include <stdint.h>

#define NEGC 1.0e9f
typedef unsigned long long ull;

// ==================== static scratch ====================
__device__ float g_epart[64 * 128];
__device__ float g_emean[128];
__device__ float g_Bmat[4096 * 128];
__device__ float g_qz[512 * 128];
__device__ float g_U[2 * 512 * 1024];
__device__ float g_qhn[4 * 8 * 128 * 128];
__device__ float g_qhnT[4 * 8 * 128 * 128];
__device__ float g_S[512 * 4096];
__device__ float g_Gpart[8 * 512 * 128];
__device__ float g_ET[128 * 32000];          // E transposed (fp32)
__device__ float g_SEpart[37 * 512 * 128];
__device__ float g_SEsum[37 * 512];

// ---- f32x2 helpers ----
__device__ __forceinline__ ull pk2(float lo, float hi) {
    ull r; asm("mov.b64 %0, {%1, %2};" : "=l"(r) : "f"(lo), "f"(hi)); return r;
}
__device__ __forceinline__ void fma2(ull &d, ull a, ull b) {
    asm("fma.rn.f32x2 %0, %1, %2, %3;" : "=l"(d) : "l"(a), "l"(b), "l"(d));
}
__device__ __forceinline__ void upk(ull v, float &lo, float &hi) {
    asm("mov.b64 {%0, %1}, %2;" : "=f"(lo), "=f"(hi) : "l"(v));
}

// ---- FMA-pipe exp (no MUFU): exp(x) = 2^(x*log2e), |x| small (<60) ----
__device__ __forceinline__ float fexp(float x) {
    float z = x * 1.4426950408889634f;
    float m = z + 12582912.0f;                    // round-to-nearest-int trick
    int ni = __float_as_int(m) - 0x4B400000;
    float f = z - (m - 12582912.0f);              // f in [-0.5, 0.5]
    float p = 0.0013333558f;
    p = fmaf(p, f, 0.0096181291f);
    p = fmaf(p, f, 0.0555041087f);
    p = fmaf(p, f, 0.2402265070f);
    p = fmaf(p, f, 0.6931471806f);
    p = fmaf(p, f, 1.0f);
    return p * __int_as_float((ni + 127) << 23);
}

// ==================== setup ====================
__global__ void k_emean_part(const float* __restrict__ E) {
    int b = blockIdx.x, t = threadIdx.x;
    int d = t & 127, h = t >> 7;
    float s = 0.f;
    for (int v = b * 500 + h; v < b * 500 + 500; v += 2) s += E[v * 128 + d];
    __shared__ float sh[256];
    sh[t] = s; __syncthreads();
    if (t < 128) g_epart[b * 128 + t] = sh[t] + sh[t + 128];
}
__global__ void k_emean_red() {
    int t = threadIdx.x;
    float s = 0.f;
    for (int b = 0; b < 64; b++) s += g_epart[b * 128 + t];
    g_emean[t] = s * (1.0f / 32000.0f);
}

__global__ void k_bmat(const float* __restrict__ T) {
    int idx = blockIdx.x * 256 + threadIdx.x;
    if (idx >= 4096 * 128) return;
    int r = idx >> 7, col = idx & 127;
    float val;
    if (r < 2048) {
        int k = r >> 10, c = (r >> 7) & 7, b = r & 127;
        val = T[((k * 128 + col) * 128 + b) * 8 + c];
    } else {
        int r2 = r - 2048;
        int k = r2 >> 10, c = (r2 >> 7) & 7, a = r2 & 127;
        val = T[((k * 128 + a) * 128 + col) * 8 + c];
    }
    g_Bmat[idx] = val;
}

// transpose E -> g_ET[d][v]. grid (250, 4), 256 thr
__global__ void k_transE(const float* __restrict__ E) {
    __shared__ float tile[128][33];
    int v0 = blockIdx.x * 128, d0 = blockIdx.y * 32, t = threadIdx.x;
    for (int idx = t; idx < 4096; idx += 256) {
        int r = idx >> 5, c = idx & 31;
        tile[r][c] = E[(size_t)(v0 + r) * 128 + d0 + c];
    }
    __syncthreads();
    for (int idx = t; idx < 4096; idx += 256) {
        int d = idx >> 7, vv = idx & 127;
        g_ET[(size_t)(d0 + d) * 32000 + v0 + vv] = tile[vv][d];
    }
}

// ---- 128-wide softmax (block of 128 thr) ----
__device__ __forceinline__ float softmax128(float raw, float* r1, float* r2) {
    int lane = threadIdx.x & 31, w = threadIdx.x >> 5;
    float m = raw;
    #pragma unroll
    for (int o = 16; o; o >>= 1) m = fmaxf(m, __shfl_xor_sync(~0u, m, o));
    if (lane == 0) r1[w] = m;
    __syncthreads();
    m = fmaxf(fmaxf(r1[0], r1[1]), fmaxf(r1[2], r1[3]));
    float e = fexp(raw - m), s = e;
    #pragma unroll
    for (int o = 16; o; o >>= 1) s += __shfl_xor_sync(~0u, s, o);
    if (lane == 0) r2[w] = s;
    __syncthreads();
    return e / (r2[0] + r2[1] + r2[2] + r2[3]);
}

__global__ void k_init_qz(const float* __restrict__ x, const int* __restrict__ mask,
                          const int* __restrict__ mmask) {
    int zi = blockIdx.x, a = threadIdx.x;
    __shared__ float r1[4], r2[4];
    float keep = mask[zi] ? 1.f : 0.f;
    float mm = (float)mmask[zi];
    float raw = (x[zi * 128 + a] * (1.f - mm) + g_emean[a] * mm) * keep;
    float p = softmax128(raw, r1, r2);
    g_qz[zi * 128 + a] = p * keep;
}

// ==================== small FFMA GEMMs ====================
__global__ void __launch_bounds__(256) k_nn64(const float* __restrict__ T, int which) {
    const float *A, *B; float *C;
    int lda, ldb, ldc, ksteps, kb;
    if (which == 0) {
        int kk = blockIdx.z;
        A = g_qz; lda = 128; B = T + kk * 131072; ldb = 1024;
        C = g_U + (size_t)kk * 524288; ldc = 1024; ksteps = 8; kb = 0;
    } else {
        int ks = blockIdx.z;
        A = g_S; lda = 4096; B = g_Bmat; ldb = 128;
        C = g_Gpart + (size_t)ks * 65536; ldc = 128; ksteps = 32; kb = ks * 512;
    }
    int m0 = blockIdx.y * 64, n0 = blockIdx.x * 64;
    __shared__ float As[16][68], Bs[16][64];
    int t = threadIdx.x, tm = t >> 4, tn = t & 15;
    ull acc[4][2];
    #pragma unroll
    for (int i = 0; i < 4; i++) { acc[i][0] = pk2(0.f, 0.f); acc[i][1] = pk2(0.f, 0.f); }
    for (int s = 0; s < ksteps; s++) {
        int k0 = kb + s * 16;
        { int r = t >> 2, c4 = (t & 3) * 4;
          float4 av = *(const float4*)&A[(size_t)(m0 + r) * lda + k0 + c4];
          As[c4][r] = av.x; As[c4 + 1][r] = av.y; As[c4 + 2][r] = av.z; As[c4 + 3][r] = av.w; }
        { int r = t >> 4, c4 = (t & 15) * 4;
          *(float4*)&Bs[r][c4] = *(const float4*)&B[(size_t)(k0 + r) * ldb + n0 + c4]; }
        __syncthreads();
        #pragma unroll
        for (int p = 0; p < 16; p++) {
            float4 a = *(const float4*)&As[p][tm * 4];
            float4 b = *(const float4*)&Bs[p][tn * 4];
            ull b01 = pk2(b.x, b.y), b23 = pk2(b.z, b.w);
            ull a0 = pk2(a.x, a.x), a1 = pk2(a.y, a.y), a2 = pk2(a.z, a.z), a3 = pk2(a.w, a.w);
            fma2(acc[0][0], a0, b01); fma2(acc[0][1], a0, b23);
            fma2(acc[1][0], a1, b01); fma2(acc[1][1], a1, b23);
            fma2(acc[2][0], a2, b01); fma2(acc[2][1], a2, b23);
            fma2(acc[3][0], a3, b01); fma2(acc[3][1], a3, b23);
        }
        __syncthreads();
    }
    #pragma unroll
    for (int i = 0; i < 4; i++) {
        float c0, c1, c2, c3;
        upk(acc[i][0], c0, c1); upk(acc[i][1], c2, c3);
        *(float4*)&C[(size_t)(m0 + tm * 4 + i) * ldc + n0 + tn * 4] = make_float4(c0, c1, c2, c3);
    }
}

__global__ void __launch_bounds__(256) k_F(const int* __restrict__ mask) {
    int zi = blockIdx.x, z = zi >> 7, i = zi & 127;
    int t = threadIdx.x;
    __shared__ float U_sh[2][1024];
    __shared__ float qz_sh[32][129];
    __shared__ float qh_sh[8][128];
    __shared__ float smax[8], ssum[8];
    for (int idx = t; idx < 2048; idx += 256) {
        int k = idx >> 10, bc = idx & 1023;
        U_sh[k][bc] = g_U[((size_t)k * 512 + zi) * 1024 + bc];
    }
    int j = t & 127, ch = t >> 7;
    int ksel = (j > i) ? 0 : 1;
    float a0 = 0.f, a1 = 0.f, a2 = 0.f, a3 = 0.f;
    const float* qzb = g_qz + z * 128 * 128;
    for (int b0 = 0; b0 < 128; b0 += 32) {
        __syncthreads();
        #pragma unroll
        for (int e = 0; e < 16; e++) {
            int lin = t + e * 256;
            int jj = lin >> 5, col = lin & 31;
            qz_sh[col][jj] = qzb[jj * 128 + b0 + col];
        }
        __syncthreads();
        #pragma unroll 8
        for (int bb = 0; bb < 32; bb++) {
            float qv = qz_sh[bb][j];
            const float* u = &U_sh[ksel][(b0 + bb) * 8 + ch * 4];
            a0 += qv * u[0]; a1 += qv * u[1]; a2 += qv * u[2]; a3 += qv * u[3];
        }
    }
    bool vi = mask[z * 128 + i] != 0, vj = mask[z * 128 + j] != 0;
    if (i == j || !vi || !vj) { a0 = a1 = a2 = a3 = -NEGC; }
    qh_sh[ch * 4 + 0][j] = a0; qh_sh[ch * 4 + 1][j] = a1;
    qh_sh[ch * 4 + 2][j] = a2; qh_sh[ch * 4 + 3][j] = a3;
    __syncthreads();
    int w = t >> 5, lane = t & 31;
    float v0 = qh_sh[w][lane], v1 = qh_sh[w][lane + 32];
    float v2 = qh_sh[w][lane + 64], v3 = qh_sh[w][lane + 96];
    float mx = fmaxf(fmaxf(v0, v1), fmaxf(v2, v3));
    #pragma unroll
    for (int o = 16; o; o >>= 1) mx = fmaxf(mx, __shfl_xor_sync(~0u, mx, o));
    float sum = fexp(v0 - mx) + fexp(v1 - mx) + fexp(v2 - mx) + fexp(v3 - mx);
    #pragma unroll
    for (int o = 16; o; o >>= 1) sum += __shfl_xor_sync(~0u, sum, o);
    if (lane == 0) { smax[w] = mx; ssum[w] = sum; }
    __syncthreads();
    float vals[4] = {a0, a1, a2, a3};
    #pragma unroll
    for (int hh = 0; hh < 4; hh++) {
        int h = ch * 4 + hh;
        float p = fexp(vals[hh] - smax[h]) / ssum[h];
        g_qhn[(((z * 8 + h) * 128 + i) << 7) + j] = p;
        g_qhnT[(((z * 8 + h) * 128 + j) << 7) + i] = p;
    }
}

__global__ void __launch_bounds__(256) k_S() {
    int zi = blockIdx.x, z = zi >> 7, i = zi & 127;
    int t = threadIdx.x;
    __shared__ float wT[128][36];
    __shared__ float qzc[32][128];
    for (int idx = t; idx < 4096; idx += 256) {
        int r = idx & 31, j = idx >> 5;
        float v; bool m;
        if (r < 16) {
            int k = r >> 3, c = r & 7;
            v = g_qhn[(((z * 8 + c) * 128 + i) << 7) + j];
            m = (k == 0) ? (j > i) : (j < i);
        } else {
            int r2 = r - 16, k = r2 >> 3, c = r2 & 7;
            v = g_qhnT[(((z * 8 + c) * 128 + i) << 7) + j];
            m = (k == 0) ? (j < i) : (j > i);
        }
        wT[j][r] = m ? v : 0.f;
    }
    int tm = t >> 5, tn = t & 31;
    ull acc[4][2];
    #pragma unroll
    for (int q = 0; q < 4; q++) { acc[q][0] = pk2(0.f, 0.f); acc[q][1] = pk2(0.f, 0.f); }
    for (int j0 = 0; j0 < 128; j0 += 32) {
        __syncthreads();
        for (int idx = t; idx < 4096; idx += 256) {
            int jl = idx >> 7, b = idx & 127;
            qzc[jl][b] = g_qz[((z * 128) + j0 + jl) * 128 + b];
        }
        __syncthreads();
        #pragma unroll 8
        for (int jl = 0; jl < 32; jl++) {
            float4 wv = *(const float4*)&wT[j0 + jl][tm * 4];
            float4 qv = *(const float4*)&qzc[jl][tn * 4];
            ull q01 = pk2(qv.x, qv.y), q23 = pk2(qv.z, qv.w);
            ull w0 = pk2(wv.x, wv.x), w1 = pk2(wv.y, wv.y), w2 = pk2(wv.z, wv.z), w3 = pk2(wv.w, wv.w);
            fma2(acc[0][0], w0, q01); fma2(acc[0][1], w0, q23);
            fma2(acc[1][0], w1, q01); fma2(acc[1][1], w1, q23);
            fma2(acc[2][0], w2, q01); fma2(acc[2][1], w2, q23);
            fma2(acc[3][0], w3, q01); fma2(acc[3][1], w3, q23);
        }
    }
    #pragma unroll
    for (int q = 0; q < 4; q++) {
        int r = tm * 4 + q;
        int base = (r < 16) ? r * 128 : 2048 + (r - 16) * 128;
        float c0, c1, c2, c3;
        upk(acc[q][0], c0, c1); upk(acc[q][1], c2, c3);
        *(float4*)&g_S[(size_t)zi * 4096 + base + tn * 4] = make_float4(c0, c1, c2, c3);
    }
}

// ---- Z update: reduce Gpart + SE combine, unary mix, softmax ----
__global__ void k_zupd(const float* __restrict__ x, const int* __restrict__ mask,
                       const int* __restrict__ mmask, int useSE) {
    int zi = blockIdx.x, d = threadIdx.x;
    __shared__ float r1[4], r2[4];
    float g = 0.f;
    #pragma unroll
    for (int p = 0; p < 8; p++) g += g_Gpart[((size_t)p * 512 + zi) * 128 + d];
    float se;
    if (useSE) {
        float num = 0.f, den = 0.f;
        for (int s = 0; s < 37; s++) {
            num += g_SEpart[((size_t)s * 512 + zi) * 128 + d];
            den += g_SEsum[s * 512 + zi];
        }
        se = num / den;
    } else se = g_emean[d];
    float mm = (float)mmask[zi];
    float raw = x[zi * 128 + d] * (1.f - mm) + se * mm + g;
    float keep = mask[zi] ? 1.f : 0.f;
    float p_ = softmax128(raw, r1, r2);
    g_qz[zi * 128 + d] = p_ * keep;
}

// ==================== fused SE: SEpart[vs] = sum_v exp(qz@E^T) * E, SEsum rowsums ====
// grid (37, 4), 256 thr, dynamic smem. 148 blocks = exactly 1 wave (1 block/SM).
// v-work in 64-wide units: 500 units total; slice vs gets 14 (vs<19) or 13 units.
#define QZT_OFF 0                      // [128 d][132 m]
#define ETD_OFF (128 * 132)            // [128 d][68 v]
#define EVD_OFF (ETD_OFF + 128 * 68)   // [64 v][132 d]
#define PS_OFF  (EVD_OFF + 64 * 132)   // [64 v][132 m]
#define SEF_SMEM ((PS_OFF + 64 * 132) * 4)

__global__ void __launch_bounds__(256) k_sef(const float* __restrict__ E) {
    extern __shared__ float sm[];
    float* qzT = sm + QZT_OFF;
    float* Etd = sm + ETD_OFF;
    float* Evd = sm + EVD_OFF;
    float* Ps  = sm + PS_OFF;
    int t = threadIdx.x;
    int vs = blockIdx.x, m0 = blockIdx.y * 128;
    int ustart = (vs < 19) ? vs * 14 : 266 + (vs - 19) * 13;
    int ucount = (vs < 19) ? 14 : 13;

    // load qz block transposed: qzT[d][m]
    {
        int m = t >> 1, d0 = (t & 1) * 64;
        const float* src = g_qz + (size_t)(m0 + m) * 128 + d0;
        #pragma unroll
        for (int q = 0; q < 16; q++) {
            float4 v = *(const float4*)(src + q * 4);
            qzT[(d0 + q * 4 + 0) * 132 + m] = v.x;
            qzT[(d0 + q * 4 + 1) * 132 + m] = v.y;
            qzT[(d0 + q * 4 + 2) * 132 + m] = v.z;
            qzT[(d0 + q * 4 + 3) * 132 + m] = v.w;
        }
    }

    int tm1 = t >> 4, tv = t & 15;          // GEMM1: 8m x 4v
    int tmg = t >> 4, tdg = t & 15;         // GEMM2: 8m x 8d
    ull acc[8][4];
    #pragma unroll
    for (int i = 0; i < 8; i++)
        #pragma unroll
        for (int q = 0; q < 4; q++) acc[i][q] = pk2(0.f, 0.f);
    float psum[8];
    #pragma unroll
    for (int i = 0; i < 8; i++) psum[i] = 0.f;

    for (int tile = 0; tile < ucount; tile++) {
        int vg = (ustart + tile) * 64;
        __syncthreads();
        {
            int d = t >> 1, vq = (t & 1) * 32;
            const float* src = g_ET + (size_t)d * 32000 + vg + vq;
            float* dst = Etd + d * 68 + vq;
            #pragma unroll
            for (int q = 0; q < 8; q++) *(float4*)(dst + q * 4) = *(const float4*)(src + q * 4);
        }
        {
            int v = t >> 2, dq = (t & 3) * 32;
            const float* src = E + (size_t)(vg + v) * 128 + dq;
            float* dst = Evd + v * 132 + dq;
            #pragma unroll
            for (int q = 0; q < 8; q++) *(float4*)(dst + q * 4) = *(const float4*)(src + q * 4);
        }
        __syncthreads();
        // GEMM1: L[8m][4v]
        ull L[8][2];
        #pragma unroll
        for (int i = 0; i < 8; i++) { L[i][0] = pk2(0.f, 0.f); L[i][1] = pk2(0.f, 0.f); }
        #pragma unroll 4
        for (int d = 0; d < 128; d++) {
            float4 a0 = *(const float4*)&qzT[d * 132 + tm1 * 8];
            float4 a1 = *(const float4*)&qzT[d * 132 + tm1 * 8 + 4];
            float4 b  = *(const float4*)&Etd[d * 68 + tv * 4];
            ull b01 = pk2(b.x, b.y), b23 = pk2(b.z, b.w);
            float av[8] = {a0.x, a0.y, a0.z, a0.w, a1.x, a1.y, a1.z, a1.w};
            #pragma unroll
            for (int i = 0; i < 8; i++) {
                ull ai = pk2(av[i], av[i]);
                fma2(L[i][0], ai, b01); fma2(L[i][1], ai, b23);
            }
        }
        // exp (FMA pipe) + write P^T[v][m] + rowsum partials
        #pragma unroll
        for (int i = 0; i < 8; i++) {
            float e0, e1, e2, e3;
            upk(L[i][0], e0, e1); upk(L[i][1], e2, e3);
            e0 = fexp(e0); e1 = fexp(e1); e2 = fexp(e2); e3 = fexp(e3);
            psum[i] += e0 + e1 + e2 + e3;
            int m = tm1 * 8 + i;
            Ps[(tv * 4 + 0) * 132 + m] = e0;
            Ps[(tv * 4 + 1) * 132 + m] = e1;
            Ps[(tv * 4 + 2) * 132 + m] = e2;
            Ps[(tv * 4 + 3) * 132 + m] = e3;
        }
        __syncthreads();
        // GEMM2: acc[8m][8d] += P^T' @ Evd
        #pragma unroll 4
        for (int v = 0; v < 64; v++) {
            float4 a0 = *(const float4*)&Ps[v * 132 + tmg * 8];
            float4 a1 = *(const float4*)&Ps[v * 132 + tmg * 8 + 4];
            float4 b0 = *(const float4*)&Evd[v * 132 + tdg * 8];
            float4 b1 = *(const float4*)&Evd[v * 132 + tdg * 8 + 4];
            ull bb[4] = {pk2(b0.x, b0.y), pk2(b0.z, b0.w), pk2(b1.x, b1.y), pk2(b1.z, b1.w)};
            float av[8] = {a0.x, a0.y, a0.z, a0.w, a1.x, a1.y, a1.z, a1.w};
            #pragma unroll
            for (int i = 0; i < 8; i++) {
                ull ai = pk2(av[i], av[i]);
                fma2(acc[i][0], ai, bb[0]); fma2(acc[i][1], ai, bb[1]);
                fma2(acc[i][2], ai, bb[2]); fma2(acc[i][3], ai, bb[3]);
            }
        }
    }
    // write acc
    #pragma unroll
    for (int i = 0; i < 8; i++) {
        float f[8];
        upk(acc[i][0], f[0], f[1]); upk(acc[i][1], f[2], f[3]);
        upk(acc[i][2], f[4], f[5]); upk(acc[i][3], f[6], f[7]);
        size_t base = ((size_t)vs * 512 + m0 + tmg * 8 + i) * 128 + tdg * 8;
        *(float4*)&g_SEpart[base]     = make_float4(f[0], f[1], f[2], f[3]);
        *(float4*)&g_SEpart[base + 4] = make_float4(f[4], f[5], f[6], f[7]);
    }
    // reduce psum across the 16 v-groups (reuse Etd area: [128 m][17])
    __syncthreads();
    float* red = Etd;
    #pragma unroll
    for (int i = 0; i < 8; i++) red[(tm1 * 8 + i) * 17 + tv] = psum[i];
    __syncthreads();
    if (t < 128) {
        float s = 0.f;
        #pragma unroll
        for (int q = 0; q < 16; q++) s += red[t * 17 + q];
        g_SEsum[vs * 512 + m0 + t] = s;
    }
}

// ==================== final out = qz @ E^T ====================
__global__ void __launch_bounds__(256) k_msg(const float* __restrict__ E, float* __restrict__ out) {
    __shared__ float As[8][128], Bs[8][128];
    int t = threadIdx.x;
    int m0 = blockIdx.y * 128, n0 = blockIdx.x * 128;
    int row = t >> 1, kq = (t & 1) * 4;
    int tm = t >> 4, tn = t & 15;
    ull acc[8][4];
    #pragma unroll
    for (int i = 0; i < 8; i++)
        #pragma unroll
        for (int q = 0; q < 4; q++) acc[i][q] = pk2(0.f, 0.f);
    for (int s = 0; s < 16; s++) {
        int k0 = s * 8;
        float4 av = *(const float4*)&g_qz[(m0 + row) * 128 + k0 + kq];
        float4 bv = *(const float4*)&E[(size_t)(n0 + row) * 128 + k0 + kq];
        __syncthreads();
        As[kq][row] = av.x; As[kq + 1][row] = av.y; As[kq + 2][row] = av.z; As[kq + 3][row] = av.w;
        Bs[kq][row] = bv.x; Bs[kq + 1][row] = bv.y; Bs[kq + 2][row] = bv.z; Bs[kq + 3][row] = bv.w;
        __syncthreads();
        #pragma unroll
        for (int p = 0; p < 8; p++) {
            float4 a0 = *(const float4*)&As[p][tm * 8], a1 = *(const float4*)&As[p][tm * 8 + 4];
            float4 b0 = *(const float4*)&Bs[p][tn * 8], b1 = *(const float4*)&Bs[p][tn * 8 + 4];
            ull bb[4] = {pk2(b0.x, b0.y), pk2(b0.z, b0.w), pk2(b1.x, b1.y), pk2(b1.z, b1.w)};
            float avv[8] = {a0.x, a0.y, a0.z, a0.w, a1.x, a1.y, a1.z, a1.w};
            #pragma unroll
            for (int i = 0; i < 8; i++) {
                ull ai = pk2(avv[i], avv[i]);
                fma2(acc[i][0], ai, bb[0]); fma2(acc[i][1], ai, bb[1]);
                fma2(acc[i][2], ai, bb[2]); fma2(acc[i][3], ai, bb[3]);
            }
        }
    }
    #pragma unroll
    for (int i = 0; i < 8; i++) {
        float f[8];
        upk(acc[i][0], f[0], f[1]); upk(acc[i][1], f[2], f[3]);
        upk(acc[i][2], f[4], f[5]); upk(acc[i][3], f[6], f[7]);
        size_t base = (size_t)(m0 + tm * 8 + i) * 32000 + n0 + tn * 8;
        *(float4*)&out[base] = make_float4(f[0], f[1], f[2], f[3]);
        *(float4*)&out[base + 4] = make_float4(f[4], f[5], f[6], f[7]);
    }
}

// ==================== launch ====================
extern "C" void kernel_launch(void* const* d_in, const int* in_sizes, int n_in,
                              void* d_out, int out_size) {
    const float* x    = (const float*)d_in[0];
    const int*   mask = (const int*)d_in[1];
    const float* E    = (const float*)d_in[2];
    const int*   mm   = (const int*)d_in[3];
    const float* T    = (const float*)d_in[4];
    float* out = (float*)d_out;

    cudaFuncSetAttribute(k_sef, cudaFuncAttributeMaxDynamicSharedMemorySize, SEF_SMEM);

    k_emean_part<<<64, 256>>>(E);
    k_emean_red<<<1, 128>>>();
    k_bmat<<<2048, 256>>>(T);
    k_transE<<<dim3(250, 4), 256>>>(E);
    k_init_qz<<<512, 128>>>(x, mask, mm);
    for (int it = 0; it < 4; it++) {
        k_nn64<<<dim3(16, 8, 2), 256>>>(T, 0);     // U = qz @ T[k]
        k_F<<<512, 256>>>(mask);                   // F + softmax -> qhn, qhnT
        k_S<<<512, 256>>>();                       // s1|s2 -> S
        k_nn64<<<dim3(2, 8, 8), 256>>>(T, 1);      // Gpart = S @ Bmat
        k_zupd<<<512, 128>>>(x, mask, mm, it > 0); // z update (+SE combine)
        if (it < 3) k_sef<<<dim3(37, 4), 256, SEF_SMEM>>>(E);   // fused SE, 1 wave
        else        k_msg<<<dim3(250, 4), 256>>>(E, out);       // final output
    }
}

// round 7
// speedup vs baseline: 1.6779x; 1.3451x over previous
#include <cuda_runtime.h>
#include <math.h>
#include <stdint.h>

#define NEGC 1.0e9f
typedef unsigned long long ull;

// ==================== static scratch ====================
__device__ float g_epart[64 * 128];
__device__ float g_emean[128];
__device__ float g_Bmat[4096 * 128];
__device__ float g_qz[512 * 128];
__device__ float g_U[2 * 512 * 1024];
__device__ float g_qhn[4 * 8 * 128 * 128];
__device__ float g_qhnT[4 * 8 * 128 * 128];
__device__ float g_S[512 * 4096];
__device__ float g_Gpart[8 * 512 * 128];
__device__ float g_ET[128 * 32000];          // E transposed (fp32)
__device__ float g_SEpart[148 * 128 * 128];  // per-block partials (compact rows)
__device__ float g_SEsum[148 * 128];
__device__ int   g_SEmt[148];
__device__ int   g_midx[512];
__device__ int   g_mpos[512];
__device__ int   g_mcount;

// ---- f32x2 helpers ----
__device__ __forceinline__ ull pk2(float lo, float hi) {
    ull r; asm("mov.b64 %0, {%1, %2};" : "=l"(r) : "f"(lo), "f"(hi)); return r;
}
__device__ __forceinline__ void fma2(ull &d, ull a, ull b) {
    asm("fma.rn.f32x2 %0, %1, %2, %3;" : "=l"(d) : "l"(a), "l"(b), "l"(d));
}
__device__ __forceinline__ void upk(ull v, float &lo, float &hi) {
    asm("mov.b64 {%0, %1}, %2;" : "=f"(lo), "=f"(hi) : "l"(v));
}

// ---- FMA-pipe exp (no MUFU). Valid for |x| < ~80. ----
__device__ __forceinline__ float fexp(float x) {
    float z = x * 1.4426950408889634f;
    float m = z + 12582912.0f;                    // round-to-nearest-int trick
    int ni = __float_as_int(m) - 0x4B400000;
    float f = z - (m - 12582912.0f);              // f in [-0.5, 0.5]
    float p = 0.0013333558f;
    p = fmaf(p, f, 0.0096181291f);
    p = fmaf(p, f, 0.0555041087f);
    p = fmaf(p, f, 0.2402265070f);
    p = fmaf(p, f, 0.6931471806f);
    p = fmaf(p, f, 1.0f);
    return p * __int_as_float((ni + 127) << 23);
}
// clamped variant for softmax deltas that can be -1e9
__device__ __forceinline__ float fexp_s(float x) { return fexp(fmaxf(x, -80.f)); }

// ==================== setup ====================
__global__ void k_emean_part(const float* __restrict__ E) {
    int b = blockIdx.x, t = threadIdx.x;
    int d = t & 127, h = t >> 7;
    float s = 0.f;
    for (int v = b * 500 + h; v < b * 500 + 500; v += 2) s += E[v * 128 + d];
    __shared__ float sh[256];
    sh[t] = s; __syncthreads();
    if (t < 128) g_epart[b * 128 + t] = sh[t] + sh[t + 128];
}
__global__ void k_emean_red() {
    int t = threadIdx.x;
    float s = 0.f;
    for (int b = 0; b < 64; b++) s += g_epart[b * 128 + t];
    g_emean[t] = s * (1.0f / 32000.0f);
}

__global__ void k_bmat(const float* __restrict__ T) {
    int idx = blockIdx.x * 256 + threadIdx.x;
    if (idx >= 4096 * 128) return;
    int r = idx >> 7, col = idx & 127;
    float val;
    if (r < 2048) {
        int k = r >> 10, c = (r >> 7) & 7, b = r & 127;
        val = T[((k * 128 + col) * 128 + b) * 8 + c];
    } else {
        int r2 = r - 2048;
        int k = r2 >> 10, c = (r2 >> 7) & 7, a = r2 & 127;
        val = T[((k * 128 + a) * 128 + col) * 8 + c];
    }
    g_Bmat[idx] = val;
}

// transpose E -> g_ET[d][v]
__global__ void k_transE(const float* __restrict__ E) {
    __shared__ float tile[128][33];
    int v0 = blockIdx.x * 128, d0 = blockIdx.y * 32, t = threadIdx.x;
    for (int idx = t; idx < 4096; idx += 256) {
        int r = idx >> 5, c = idx & 31;
        tile[r][c] = E[(size_t)(v0 + r) * 128 + d0 + c];
    }
    __syncthreads();
    for (int idx = t; idx < 4096; idx += 256) {
        int d = idx >> 7, vv = idx & 127;
        g_ET[(size_t)(d0 + d) * 32000 + v0 + vv] = tile[vv][d];
    }
}

// compact list of rows needing SE (mm!=0 && mask!=0). 1 block x 512 thr.
__global__ void k_midx(const int* __restrict__ mask, const int* __restrict__ mmask) {
    __shared__ int pref[512];
    int t = threadIdx.x;
    int f = (mmask[t] != 0 && mask[t] != 0) ? 1 : 0;
    pref[t] = f;
    __syncthreads();
    for (int o = 1; o < 512; o <<= 1) {
        int v = (t >= o) ? pref[t - o] : 0;
        __syncthreads();
        pref[t] += v;
        __syncthreads();
    }
    if (f) { int pos = pref[t] - 1; g_midx[pos] = t; g_mpos[t] = pos; }
    else g_mpos[t] = -1;
    if (t == 511) g_mcount = pref[511];
}

// ---- 128-wide softmax (block of 128 thr) ----
__device__ __forceinline__ float softmax128(float raw, float* r1, float* r2) {
    int lane = threadIdx.x & 31, w = threadIdx.x >> 5;
    float m = raw;
    #pragma unroll
    for (int o = 16; o; o >>= 1) m = fmaxf(m, __shfl_xor_sync(~0u, m, o));
    if (lane == 0) r1[w] = m;
    __syncthreads();
    m = fmaxf(fmaxf(r1[0], r1[1]), fmaxf(r1[2], r1[3]));
    float e = fexp_s(raw - m), s = e;
    #pragma unroll
    for (int o = 16; o; o >>= 1) s += __shfl_xor_sync(~0u, s, o);
    if (lane == 0) r2[w] = s;
    __syncthreads();
    return e / (r2[0] + r2[1] + r2[2] + r2[3]);
}

__global__ void k_init_qz(const float* __restrict__ x, const int* __restrict__ mask,
                          const int* __restrict__ mmask) {
    int zi = blockIdx.x, a = threadIdx.x;
    __shared__ float r1[4], r2[4];
    float keep = mask[zi] ? 1.f : 0.f;
    float mm = (float)mmask[zi];
    float raw = (x[zi * 128 + a] * (1.f - mm) + g_emean[a] * mm) * keep;
    float p = softmax128(raw, r1, r2);
    g_qz[zi * 128 + a] = p * keep;
}

// ==================== small FFMA GEMMs ====================
__global__ void __launch_bounds__(256) k_nn64(const float* __restrict__ T, int which) {
    const float *A, *B; float *C;
    int lda, ldb, ldc, ksteps, kb;
    if (which == 0) {
        int kk = blockIdx.z;
        A = g_qz; lda = 128; B = T + kk * 131072; ldb = 1024;
        C = g_U + (size_t)kk * 524288; ldc = 1024; ksteps = 8; kb = 0;
    } else {
        int ks = blockIdx.z;
        A = g_S; lda = 4096; B = g_Bmat; ldb = 128;
        C = g_Gpart + (size_t)ks * 65536; ldc = 128; ksteps = 32; kb = ks * 512;
    }
    int m0 = blockIdx.y * 64, n0 = blockIdx.x * 64;
    __shared__ float As[16][68], Bs[16][64];
    int t = threadIdx.x, tm = t >> 4, tn = t & 15;
    ull acc[4][2];
    #pragma unroll
    for (int i = 0; i < 4; i++) { acc[i][0] = pk2(0.f, 0.f); acc[i][1] = pk2(0.f, 0.f); }
    for (int s = 0; s < ksteps; s++) {
        int k0 = kb + s * 16;
        { int r = t >> 2, c4 = (t & 3) * 4;
          float4 av = *(const float4*)&A[(size_t)(m0 + r) * lda + k0 + c4];
          As[c4][r] = av.x; As[c4 + 1][r] = av.y; As[c4 + 2][r] = av.z; As[c4 + 3][r] = av.w; }
        { int r = t >> 4, c4 = (t & 15) * 4;
          *(float4*)&Bs[r][c4] = *(const float4*)&B[(size_t)(k0 + r) * ldb + n0 + c4]; }
        __syncthreads();
        #pragma unroll
        for (int p = 0; p < 16; p++) {
            float4 a = *(const float4*)&As[p][tm * 4];
            float4 b = *(const float4*)&Bs[p][tn * 4];
            ull b01 = pk2(b.x, b.y), b23 = pk2(b.z, b.w);
            ull a0 = pk2(a.x, a.x), a1 = pk2(a.y, a.y), a2 = pk2(a.z, a.z), a3 = pk2(a.w, a.w);
            fma2(acc[0][0], a0, b01); fma2(acc[0][1], a0, b23);
            fma2(acc[1][0], a1, b01); fma2(acc[1][1], a1, b23);
            fma2(acc[2][0], a2, b01); fma2(acc[2][1], a2, b23);
            fma2(acc[3][0], a3, b01); fma2(acc[3][1], a3, b23);
        }
        __syncthreads();
    }
    #pragma unroll
    for (int i = 0; i < 4; i++) {
        float c0, c1, c2, c3;
        upk(acc[i][0], c0, c1); upk(acc[i][1], c2, c3);
        *(float4*)&C[(size_t)(m0 + tm * 4 + i) * ldc + n0 + tn * 4] = make_float4(c0, c1, c2, c3);
    }
}

__global__ void __launch_bounds__(256) k_F(const int* __restrict__ mask) {
    int zi = blockIdx.x, z = zi >> 7, i = zi & 127;
    int t = threadIdx.x;
    __shared__ float U_sh[2][1024];
    __shared__ float qz_sh[32][129];
    __shared__ float qh_sh[8][128];
    __shared__ float smax[8], ssum[8];
    for (int idx = t; idx < 2048; idx += 256) {
        int k = idx >> 10, bc = idx & 1023;
        U_sh[k][bc] = g_U[((size_t)k * 512 + zi) * 1024 + bc];
    }
    int j = t & 127, ch = t >> 7;
    int ksel = (j > i) ? 0 : 1;
    float a0 = 0.f, a1 = 0.f, a2 = 0.f, a3 = 0.f;
    const float* qzb = g_qz + z * 128 * 128;
    for (int b0 = 0; b0 < 128; b0 += 32) {
        __syncthreads();
        #pragma unroll
        for (int e = 0; e < 16; e++) {
            int lin = t + e * 256;
            int jj = lin >> 5, col = lin & 31;
            qz_sh[col][jj] = qzb[jj * 128 + b0 + col];
        }
        __syncthreads();
        #pragma unroll 8
        for (int bb = 0; bb < 32; bb++) {
            float qv = qz_sh[bb][j];
            const float* u = &U_sh[ksel][(b0 + bb) * 8 + ch * 4];
            a0 += qv * u[0]; a1 += qv * u[1]; a2 += qv * u[2]; a3 += qv * u[3];
        }
    }
    bool vi = mask[z * 128 + i] != 0, vj = mask[z * 128 + j] != 0;
    if (i == j || !vi || !vj) { a0 = a1 = a2 = a3 = -NEGC; }
    qh_sh[ch * 4 + 0][j] = a0; qh_sh[ch * 4 + 1][j] = a1;
    qh_sh[ch * 4 + 2][j] = a2; qh_sh[ch * 4 + 3][j] = a3;
    __syncthreads();
    int w = t >> 5, lane = t & 31;
    float v0 = qh_sh[w][lane], v1 = qh_sh[w][lane + 32];
    float v2 = qh_sh[w][lane + 64], v3 = qh_sh[w][lane + 96];
    float mx = fmaxf(fmaxf(v0, v1), fmaxf(v2, v3));
    #pragma unroll
    for (int o = 16; o; o >>= 1) mx = fmaxf(mx, __shfl_xor_sync(~0u, mx, o));
    float sum = fexp_s(v0 - mx) + fexp_s(v1 - mx) + fexp_s(v2 - mx) + fexp_s(v3 - mx);
    #pragma unroll
    for (int o = 16; o; o >>= 1) sum += __shfl_xor_sync(~0u, sum, o);
    if (lane == 0) { smax[w] = mx; ssum[w] = sum; }
    __syncthreads();
    float vals[4] = {a0, a1, a2, a3};
    #pragma unroll
    for (int hh = 0; hh < 4; hh++) {
        int h = ch * 4 + hh;
        float p = fexp_s(vals[hh] - smax[h]) / ssum[h];
        g_qhn[(((z * 8 + h) * 128 + i) << 7) + j] = p;
        g_qhnT[(((z * 8 + h) * 128 + j) << 7) + i] = p;
    }
}

__global__ void __launch_bounds__(256) k_S() {
    int zi = blockIdx.x, z = zi >> 7, i = zi & 127;
    int t = threadIdx.x;
    __shared__ float wT[128][36];
    __shared__ float qzc[32][128];
    for (int idx = t; idx < 4096; idx += 256) {
        int r = idx & 31, j = idx >> 5;
        float v; bool m;
        if (r < 16) {
            int k = r >> 3, c = r & 7;
            v = g_qhn[(((z * 8 + c) * 128 + i) << 7) + j];
            m = (k == 0) ? (j > i) : (j < i);
        } else {
            int r2 = r - 16, k = r2 >> 3, c = r2 & 7;
            v = g_qhnT[(((z * 8 + c) * 128 + i) << 7) + j];
            m = (k == 0) ? (j < i) : (j > i);
        }
        wT[j][r] = m ? v : 0.f;
    }
    int tm = t >> 5, tn = t & 31;
    ull acc[4][2];
    #pragma unroll
    for (int q = 0; q < 4; q++) { acc[q][0] = pk2(0.f, 0.f); acc[q][1] = pk2(0.f, 0.f); }
    for (int j0 = 0; j0 < 128; j0 += 32) {
        __syncthreads();
        for (int idx = t; idx < 4096; idx += 256) {
            int jl = idx >> 7, b = idx & 127;
            qzc[jl][b] = g_qz[((z * 128) + j0 + jl) * 128 + b];
        }
        __syncthreads();
        #pragma unroll 8
        for (int jl = 0; jl < 32; jl++) {
            float4 wv = *(const float4*)&wT[j0 + jl][tm * 4];
            float4 qv = *(const float4*)&qzc[jl][tn * 4];
            ull q01 = pk2(qv.x, qv.y), q23 = pk2(qv.z, qv.w);
            ull w0 = pk2(wv.x, wv.x), w1 = pk2(wv.y, wv.y), w2 = pk2(wv.z, wv.z), w3 = pk2(wv.w, wv.w);
            fma2(acc[0][0], w0, q01); fma2(acc[0][1], w0, q23);
            fma2(acc[1][0], w1, q01); fma2(acc[1][1], w1, q23);
            fma2(acc[2][0], w2, q01); fma2(acc[2][1], w2, q23);
            fma2(acc[3][0], w3, q01); fma2(acc[3][1], w3, q23);
        }
    }
    #pragma unroll
    for (int q = 0; q < 4; q++) {
        int r = tm * 4 + q;
        int base = (r < 16) ? r * 128 : 2048 + (r - 16) * 128;
        float c0, c1, c2, c3;
        upk(acc[q][0], c0, c1); upk(acc[q][1], c2, c3);
        *(float4*)&g_S[(size_t)zi * 4096 + base + tn * 4] = make_float4(c0, c1, c2, c3);
    }
}

// ---- Z update: reduce Gpart + compact-SE combine, unary mix, softmax ----
__global__ void k_zupd(const float* __restrict__ x, const int* __restrict__ mask,
                       const int* __restrict__ mmask, int useSE) {
    int zi = blockIdx.x, d = threadIdx.x;
    __shared__ float r1[4], r2[4];
    __shared__ int smt[148];
    if (useSE) {
        for (int q = d; q < 148; q += 128) smt[q] = g_SEmt[q];
    }
    __syncthreads();
    float g = 0.f;
    #pragma unroll
    for (int p = 0; p < 8; p++) g += g_Gpart[((size_t)p * 512 + zi) * 128 + d];
    float mm = (float)mmask[zi];
    float se = 0.f;
    if (mm != 0.f) {
        if (useSE) {
            int pos = g_mpos[zi];
            if (pos >= 0) {
                int mt = pos >> 7, row = pos & 127;
                float num = 0.f, den = 0.f;
                for (int bb = 0; bb < 148; bb++) {
                    if (smt[bb] == mt) {
                        num += g_SEpart[((size_t)bb * 128 + row) * 128 + d];
                        den += g_SEsum[bb * 128 + row];
                    }
                }
                se = num / den;
            }
        } else se = g_emean[d];
    }
    float raw = x[zi * 128 + d] * (1.f - mm) + se * mm + g;
    float keep = mask[zi] ? 1.f : 0.f;
    float p_ = softmax128(raw, r1, r2);
    g_qz[zi * 128 + d] = p_ * keep;
}

// ==================== fused SE on compacted masked rows ====================
// grid 148 blocks x 256 thr. Runtime work distribution over (ntiles x 500 v-units).
#define QZT_OFF 0                      // [128 d][132 m]
#define ETD_OFF (128 * 132)            // [128 d][68 v]
#define EVD_OFF (ETD_OFF + 128 * 68)   // [64 v][132 d]
#define PS_OFF  (EVD_OFF + 64 * 132)   // [64 v][132 m]
#define SEF_SMEM ((PS_OFF + 64 * 132) * 4)

__global__ void __launch_bounds__(256) k_sef(const float* __restrict__ E) {
    int count = g_mcount;
    if (count == 0) return;
    int ntiles = (count + 127) >> 7;
    int b = blockIdx.x;
    int mt = (b * ntiles) / 148;
    int gb0 = (mt * 148 + ntiles - 1) / ntiles;
    int gb1 = ((mt + 1) * 148 + ntiles - 1) / ntiles;
    int gsz = gb1 - gb0, li = b - gb0;
    int ustart = (li * 500) / gsz;
    int ucount = ((li + 1) * 500) / gsz - ustart;
    int m0 = mt * 128;

    extern __shared__ float sm[];
    float* qzT = sm + QZT_OFF;
    float* Etd = sm + ETD_OFF;
    float* Evd = sm + EVD_OFF;
    float* Ps  = sm + PS_OFF;
    int t = threadIdx.x;

    // load qz (compacted rows) transposed: qzT[d][m]
    {
        int m = t >> 1, d0 = (t & 1) * 64;
        int pos = m0 + m;
        int zi = (pos < count) ? g_midx[pos] : 0;
        const float* src = g_qz + (size_t)zi * 128 + d0;
        #pragma unroll
        for (int q = 0; q < 16; q++) {
            float4 v = *(const float4*)(src + q * 4);
            qzT[(d0 + q * 4 + 0) * 132 + m] = v.x;
            qzT[(d0 + q * 4 + 1) * 132 + m] = v.y;
            qzT[(d0 + q * 4 + 2) * 132 + m] = v.z;
            qzT[(d0 + q * 4 + 3) * 132 + m] = v.w;
        }
    }

    int tm1 = t >> 4, tv = t & 15;          // GEMM1: 8m x 4v
    int tmg = t >> 4, tdg = t & 15;         // GEMM2: 8m x 8d
    ull acc[8][4];
    #pragma unroll
    for (int i = 0; i < 8; i++)
        #pragma unroll
        for (int q = 0; q < 4; q++) acc[i][q] = pk2(0.f, 0.f);
    float psum[8];
    #pragma unroll
    for (int i = 0; i < 8; i++) psum[i] = 0.f;

    for (int tile = 0; tile < ucount; tile++) {
        int vg = (ustart + tile) * 64;
        __syncthreads();
        {
            int d = t >> 1, vq = (t & 1) * 32;
            const float* src = g_ET + (size_t)d * 32000 + vg + vq;
            float* dst = Etd + d * 68 + vq;
            #pragma unroll
            for (int q = 0; q < 8; q++) *(float4*)(dst + q * 4) = *(const float4*)(src + q * 4);
        }
        {
            int v = t >> 2, dq = (t & 3) * 32;
            const float* src = E + (size_t)(vg + v) * 128 + dq;
            float* dst = Evd + v * 132 + dq;
            #pragma unroll
            for (int q = 0; q < 8; q++) *(float4*)(dst + q * 4) = *(const float4*)(src + q * 4);
        }
        __syncthreads();
        // GEMM1: L[8m][4v]
        ull L[8][2];
        #pragma unroll
        for (int i = 0; i < 8; i++) { L[i][0] = pk2(0.f, 0.f); L[i][1] = pk2(0.f, 0.f); }
        #pragma unroll 4
        for (int d = 0; d < 128; d++) {
            float4 a0 = *(const float4*)&qzT[d * 132 + tm1 * 8];
            float4 a1 = *(const float4*)&qzT[d * 132 + tm1 * 8 + 4];
            float4 bq = *(const float4*)&Etd[d * 68 + tv * 4];
            ull b01 = pk2(bq.x, bq.y), b23 = pk2(bq.z, bq.w);
            float av[8] = {a0.x, a0.y, a0.z, a0.w, a1.x, a1.y, a1.z, a1.w};
            #pragma unroll
            for (int i = 0; i < 8; i++) {
                ull ai = pk2(av[i], av[i]);
                fma2(L[i][0], ai, b01); fma2(L[i][1], ai, b23);
            }
        }
        // exp (FMA pipe) + write P^T[v][m] + rowsum partials
        #pragma unroll
        for (int i = 0; i < 8; i++) {
            float e0, e1, e2, e3;
            upk(L[i][0], e0, e1); upk(L[i][1], e2, e3);
            e0 = fexp(e0); e1 = fexp(e1); e2 = fexp(e2); e3 = fexp(e3);
            psum[i] += e0 + e1 + e2 + e3;
            int m = tm1 * 8 + i;
            Ps[(tv * 4 + 0) * 132 + m] = e0;
            Ps[(tv * 4 + 1) * 132 + m] = e1;
            Ps[(tv * 4 + 2) * 132 + m] = e2;
            Ps[(tv * 4 + 3) * 132 + m] = e3;
        }
        __syncthreads();
        // GEMM2: acc[8m][8d] += P^T' @ Evd
        #pragma unroll 4
        for (int v = 0; v < 64; v++) {
            float4 a0 = *(const float4*)&Ps[v * 132 + tmg * 8];
            float4 a1 = *(const float4*)&Ps[v * 132 + tmg * 8 + 4];
            float4 b0 = *(const float4*)&Evd[v * 132 + tdg * 8];
            float4 b1 = *(const float4*)&Evd[v * 132 + tdg * 8 + 4];
            ull bb[4] = {pk2(b0.x, b0.y), pk2(b0.z, b0.w), pk2(b1.x, b1.y), pk2(b1.z, b1.w)};
            float av[8] = {a0.x, a0.y, a0.z, a0.w, a1.x, a1.y, a1.z, a1.w};
            #pragma unroll
            for (int i = 0; i < 8; i++) {
                ull ai = pk2(av[i], av[i]);
                fma2(acc[i][0], ai, bb[0]); fma2(acc[i][1], ai, bb[1]);
                fma2(acc[i][2], ai, bb[2]); fma2(acc[i][3], ai, bb[3]);
            }
        }
    }
    // write acc to per-block partial slot
    #pragma unroll
    for (int i = 0; i < 8; i++) {
        float f[8];
        upk(acc[i][0], f[0], f[1]); upk(acc[i][1], f[2], f[3]);
        upk(acc[i][2], f[4], f[5]); upk(acc[i][3], f[6], f[7]);
        size_t base = ((size_t)b * 128 + tmg * 8 + i) * 128 + tdg * 8;
        *(float4*)&g_SEpart[base]     = make_float4(f[0], f[1], f[2], f[3]);
        *(float4*)&g_SEpart[base + 4] = make_float4(f[4], f[5], f[6], f[7]);
    }
    // reduce psum across the 16 v-groups (reuse Etd area: [128 m][17])
    __syncthreads();
    float* red = Etd;
    #pragma unroll
    for (int i = 0; i < 8; i++) red[(tm1 * 8 + i) * 17 + tv] = psum[i];
    __syncthreads();
    if (t < 128) {
        float s = 0.f;
        #pragma unroll
        for (int q = 0; q < 16; q++) s += red[t * 17 + q];
        g_SEsum[b * 128 + t] = s;
    }
    if (t == 0) g_SEmt[b] = mt;
}

// ==================== final out = qz @ E^T ====================
__global__ void __launch_bounds__(256) k_msg(const float* __restrict__ E, float* __restrict__ out) {
    __shared__ float As[8][128], Bs[8][128];
    int t = threadIdx.x;
    int m0 = blockIdx.y * 128, n0 = blockIdx.x * 128;
    int row = t >> 1, kq = (t & 1) * 4;
    int tm = t >> 4, tn = t & 15;
    ull acc[8][4];
    #pragma unroll
    for (int i = 0; i < 8; i++)
        #pragma unroll
        for (int q = 0; q < 4; q++) acc[i][q] = pk2(0.f, 0.f);
    for (int s = 0; s < 16; s++) {
        int k0 = s * 8;
        float4 av = *(const float4*)&g_qz[(m0 + row) * 128 + k0 + kq];
        float4 bv = *(const float4*)&E[(size_t)(n0 + row) * 128 + k0 + kq];
        __syncthreads();
        As[kq][row] = av.x; As[kq + 1][row] = av.y; As[kq + 2][row] = av.z; As[kq + 3][row] = av.w;
        Bs[kq][row] = bv.x; Bs[kq + 1][row] = bv.y; Bs[kq + 2][row] = bv.z; Bs[kq + 3][row] = bv.w;
        __syncthreads();
        #pragma unroll
        for (int p = 0; p < 8; p++) {
            float4 a0 = *(const float4*)&As[p][tm * 8], a1 = *(const float4*)&As[p][tm * 8 + 4];
            float4 b0 = *(const float4*)&Bs[p][tn * 8], b1 = *(const float4*)&Bs[p][tn * 8 + 4];
            ull bb[4] = {pk2(b0.x, b0.y), pk2(b0.z, b0.w), pk2(b1.x, b1.y), pk2(b1.z, b1.w)};
            float avv[8] = {a0.x, a0.y, a0.z, a0.w, a1.x, a1.y, a1.z, a1.w};
            #pragma unroll
            for (int i = 0; i < 8; i++) {
                ull ai = pk2(avv[i], avv[i]);
                fma2(acc[i][0], ai, bb[0]); fma2(acc[i][1], ai, bb[1]);
                fma2(acc[i][2], ai, bb[2]); fma2(acc[i][3], ai, bb[3]);
            }
        }
    }
    #pragma unroll
    for (int i = 0; i < 8; i++) {
        float f[8];
        upk(acc[i][0], f[0], f[1]); upk(acc[i][1], f[2], f[3]);
        upk(acc[i][2], f[4], f[5]); upk(acc[i][3], f[6], f[7]);
        size_t base = (size_t)(m0 + tm * 8 + i) * 32000 + n0 + tn * 8;
        *(float4*)&out[base] = make_float4(f[0], f[1], f[2], f[3]);
        *(float4*)&out[base + 4] = make_float4(f[4], f[5], f[6], f[7]);
    }
}

// ==================== launch ====================
extern "C" void kernel_launch(void* const* d_in, const int* in_sizes, int n_in,
                              void* d_out, int out_size) {
    const float* x    = (const float*)d_in[0];
    const int*   mask = (const int*)d_in[1];
    const float* E    = (const float*)d_in[2];
    const int*   mm   = (const int*)d_in[3];
    const float* T    = (const float*)d_in[4];
    float* out = (float*)d_out;

    cudaFuncSetAttribute(k_sef, cudaFuncAttributeMaxDynamicSharedMemorySize, SEF_SMEM);

    k_emean_part<<<64, 256>>>(E);
    k_emean_red<<<1, 128>>>();
    k_bmat<<<2048, 256>>>(T);
    k_transE<<<dim3(250, 4), 256>>>(E);
    k_midx<<<1, 512>>>(mask, mm);
    k_init_qz<<<512, 128>>>(x, mask, mm);
    for (int it = 0; it < 4; it++) {
        k_nn64<<<dim3(16, 8, 2), 256>>>(T, 0);     // U = qz @ T[k]
        k_F<<<512, 256>>>(mask);                   // F + softmax -> qhn, qhnT
        k_S<<<512, 256>>>();                       // s1|s2 -> S
        k_nn64<<<dim3(2, 8, 8), 256>>>(T, 1);      // Gpart = S @ Bmat
        k_zupd<<<512, 128>>>(x, mask, mm, it > 0); // z update (+compact SE combine)
        if (it < 3) k_sef<<<148, 256, SEF_SMEM>>>(E);   // fused SE, masked rows only
        else        k_msg<<<dim3(250, 4), 256>>>(E, out);  // final output
    }
}